// round 5
// baseline (speedup 1.0000x reference)
#include <cuda_runtime.h>
#include <cstdint>

// 2-bit quantized embedding gather.
// input_ids: [64,4096] **int32** (JAX x64-disabled downgrades int64->int32!)
// bit_arr: [3.2M] int32 ; codebook: [4] fp32 ; out: [262144, 128] fp32.
//
// Structure: pos = token*128 + dim, bitpos = pos*2 -> each token's 128 codes
// are an aligned 8-word (32-byte) block at word token*8. Lane t of a warp
// handles dims 4t..4t+3 = byte t of that block.

__global__ __launch_bounds__(256)
void embed2bit_kernel(const int* __restrict__ ids,
                      const unsigned int* __restrict__ bits,
                      const float* __restrict__ cb,
                      float4* __restrict__ out,
                      int n_tokens)
{
    int warp = (blockIdx.x * blockDim.x + threadIdx.x) >> 5;
    int lane = threadIdx.x & 31;
    if (warp >= n_tokens) return;

    // Warp-uniform token id (broadcast load, 1 wavefront).
    unsigned int tok = (unsigned int)__ldg(&ids[warp]);

    // 4 lanes share each of the 8 words of the token's 32-byte code block.
    unsigned int w = __ldg(&bits[(size_t)tok * 8 + (lane >> 2)]);
    unsigned int byte = (w >> ((lane & 3) * 8)) & 0xFFu;

    // Codebook in registers; decode via predicated selects, no memory LUT.
    float c0 = __ldg(&cb[0]);
    float c1 = __ldg(&cb[1]);
    float c2 = __ldg(&cb[2]);
    float c3 = __ldg(&cb[3]);

    #define DECODE(c) (((c) & 1u) ? (((c) & 2u) ? c3 : c1) \
                                  : (((c) & 2u) ? c2 : c0))
    float4 v;
    v.x = DECODE(((byte >> 0) & 3u));
    v.y = DECODE(((byte >> 2) & 3u));
    v.z = DECODE(((byte >> 4) & 3u));
    v.w = DECODE(((byte >> 6) & 3u));
    #undef DECODE

    // Warp writes 32 consecutive float4 = 512 B fully coalesced.
    out[(size_t)warp * 32 + lane] = v;
}

extern "C" void kernel_launch(void* const* d_in, const int* in_sizes, int n_in,
                              void* d_out, int out_size)
{
    const int*          ids  = (const int*)d_in[0];
    const unsigned int* bits = (const unsigned int*)d_in[1];
    const float*        cb   = (const float*)d_in[2];
    float4*             out  = (float4*)d_out;

    int n_tokens = in_sizes[0];              // 64*4096 = 262144
    int threads = 256;                       // 8 warps/block
    int warps_per_block = threads / 32;
    int blocks = (n_tokens + warps_per_block - 1) / warps_per_block;

    embed2bit_kernel<<<blocks, threads>>>(ids, bits, cb, out, n_tokens);
}

// round 6
// speedup vs baseline: 1.3337x; 1.3337x over previous
#include <cuda_runtime.h>
#include <cstdint>

// 2-bit quantized embedding gather — R6: 4 tokens per warp for MLP.
// input_ids: [262144] int32 ; bit_arr: [3.2M] int32 ; codebook: [4] fp32
// out: [262144, 128] fp32.
//
// pos = token*128 + dim, bitpos = pos*2 -> each token's 128 codes are an
// aligned 8-word (32B) block at word token*8. Lane t handles dims 4t..4t+3
// = byte t of that block.
//
// R5 ncu: DRAM 28.5%, L2 30.5%, issue 31% -> latency-bound, MLP=1 chain
// (ids -> bits -> store). This version: one int4 id load per warp, then 4
// independent bits loads + 4 independent streaming stores.

#define TOK_PER_WARP 4

__global__ __launch_bounds__(256)
void embed2bit_kernel(const int4* __restrict__ ids4,
                      const unsigned int* __restrict__ bits,
                      const float* __restrict__ cb,
                      float4* __restrict__ out,
                      int n_tokens)
{
    int warp = (blockIdx.x * blockDim.x + threadIdx.x) >> 5;
    int lane = threadIdx.x & 31;

    int tok_base = warp * TOK_PER_WARP;
    if (tok_base >= n_tokens) return;

    // One warp-uniform 16B load = 4 token ids (broadcast, 1 wavefront).
    int4 t4 = __ldg(&ids4[warp]);
    unsigned int tok[TOK_PER_WARP] = {
        (unsigned int)t4.x, (unsigned int)t4.y,
        (unsigned int)t4.z, (unsigned int)t4.w };

    // 4 independent code-block loads (MLP=4). 4 lanes share each word.
    unsigned int w[TOK_PER_WARP];
    #pragma unroll
    for (int j = 0; j < TOK_PER_WARP; j++)
        w[j] = __ldg(&bits[(size_t)tok[j] * 8 + (lane >> 2)]);

    // Codebook in registers; decode via predicated selects, no memory LUT.
    float c0 = __ldg(&cb[0]);
    float c1 = __ldg(&cb[1]);
    float c2 = __ldg(&cb[2]);
    float c3 = __ldg(&cb[3]);

    #define DECODE(c) (((c) & 1u) ? (((c) & 2u) ? c3 : c1) \
                                  : (((c) & 2u) ? c2 : c0))
    unsigned int sh = (lane & 3) * 8;

    #pragma unroll
    for (int j = 0; j < TOK_PER_WARP; j++) {
        unsigned int byte = (w[j] >> sh) & 0xFFu;
        float4 v;
        v.x = DECODE(((byte >> 0) & 3u));
        v.y = DECODE(((byte >> 2) & 3u));
        v.z = DECODE(((byte >> 4) & 3u));
        v.w = DECODE(((byte >> 6) & 3u));
        // 512 B fully-coalesced streaming store (write-once data: keep out of L2).
        __stcs(&out[(size_t)(tok_base + j) * 32 + lane], v);
    }
    #undef DECODE
}

extern "C" void kernel_launch(void* const* d_in, const int* in_sizes, int n_in,
                              void* d_out, int out_size)
{
    const int4*         ids4 = (const int4*)d_in[0];
    const unsigned int* bits = (const unsigned int*)d_in[1];
    const float*        cb   = (const float*)d_in[2];
    float4*             out  = (float4*)d_out;

    int n_tokens = in_sizes[0];                       // 262144 (divisible by 4)
    int warps = (n_tokens + TOK_PER_WARP - 1) / TOK_PER_WARP;
    int threads = 256;                                // 8 warps/block
    int blocks = (warps + 7) / 8;

    embed2bit_kernel<<<blocks, threads>>>(ids4, bits, cb, out, n_tokens);
}

// round 8
// speedup vs baseline: 1.8298x; 1.3720x over previous
#include <cuda_runtime.h>
#include <cstdint>

// 2-bit quantized embedding gather — R7 resubmit (infra failure last round).
// input_ids: [262144] int32 ; bit_arr: [3.2M] int32 ; codebook: [4] fp32
// out: [262144, 128] fp32.
//
// pos = token*128 + dim, bitpos = pos*2 -> each token's 128 codes are an
// aligned 8-word (32B) block at word token*8. Lane t handles dims 4t..4t+3
// = byte t of that block.
//
// R6 ncu: DRAM 32.6%, L1 70%, issue 39.5% -> latency still partially
// exposed. This version: 2 independent int4 id loads, 8 independent bits
// loads (MLP=8), 8 independent 512B coalesced streaming stores.

#define TOK_PER_WARP 8

__global__ __launch_bounds__(256)
void embed2bit_kernel(const int4* __restrict__ ids4,
                      const unsigned int* __restrict__ bits,
                      const float* __restrict__ cb,
                      float4* __restrict__ out,
                      int n_tokens)
{
    int warp = (blockIdx.x * blockDim.x + threadIdx.x) >> 5;
    int lane = threadIdx.x & 31;

    int tok_base = warp * TOK_PER_WARP;
    if (tok_base >= n_tokens) return;

    // Two independent warp-uniform 16B loads = 8 token ids.
    int4 ta = __ldg(&ids4[warp * 2 + 0]);
    int4 tb = __ldg(&ids4[warp * 2 + 1]);
    unsigned int tok[TOK_PER_WARP] = {
        (unsigned int)ta.x, (unsigned int)ta.y,
        (unsigned int)ta.z, (unsigned int)ta.w,
        (unsigned int)tb.x, (unsigned int)tb.y,
        (unsigned int)tb.z, (unsigned int)tb.w };

    // 8 independent code-block loads (MLP=8). 4 lanes share each word.
    unsigned int w[TOK_PER_WARP];
    #pragma unroll
    for (int j = 0; j < TOK_PER_WARP; j++)
        w[j] = __ldg(&bits[(size_t)tok[j] * 8 + (lane >> 2)]);

    // Codebook in registers; decode via predicated selects, no memory LUT.
    float c0 = __ldg(&cb[0]);
    float c1 = __ldg(&cb[1]);
    float c2 = __ldg(&cb[2]);
    float c3 = __ldg(&cb[3]);

    #define DECODE(c) (((c) & 1u) ? (((c) & 2u) ? c3 : c1) \
                                  : (((c) & 2u) ? c2 : c0))
    unsigned int sel = lane & 3;   // which byte of the word this lane owns

    #pragma unroll
    for (int j = 0; j < TOK_PER_WARP; j++) {
        unsigned int byte = __byte_perm(w[j], 0u, sel) & 0xFFu;  // 1 PRMT
        float4 v;
        v.x = DECODE(((byte >> 0) & 3u));
        v.y = DECODE(((byte >> 2) & 3u));
        v.z = DECODE(((byte >> 4) & 3u));
        v.w = DECODE(((byte >> 6) & 3u));
        // 512 B fully-coalesced streaming store (write-once: bypass L2 residency).
        __stcs(&out[(size_t)(tok_base + j) * 32 + lane], v);
    }
    #undef DECODE
}

extern "C" void kernel_launch(void* const* d_in, const int* in_sizes, int n_in,
                              void* d_out, int out_size)
{
    const int4*         ids4 = (const int4*)d_in[0];
    const unsigned int* bits = (const unsigned int*)d_in[1];
    const float*        cb   = (const float*)d_in[2];
    float4*             out  = (float4*)d_out;

    int n_tokens = in_sizes[0];                       // 262144 (divisible by 8)
    int warps = (n_tokens + TOK_PER_WARP - 1) / TOK_PER_WARP;
    int threads = 256;                                // 8 warps/block
    int blocks = (warps + 7) / 8;

    embed2bit_kernel<<<blocks, threads>>>(ids4, bits, cb, out, n_tokens);
}